// round 15
// baseline (speedup 1.0000x reference)
#include <cuda_runtime.h>
#include <math.h>

typedef unsigned long long ull;

#define BSZ    64
#define HD     256
#define ED     512
#define VD     32000
#define NGRP   500
#define SOS    1
#define EOS    2
#define MAXLEN 48
#define NEG_INF __int_as_float(0xff800000)

// ---------------- persistent device state ----------------
__device__ int g_alldone;
__device__ ull g_done;
__device__ int g_tok[BSZ];
__device__ __align__(16) float g_encT[256 * BSZ];
__device__ __align__(16) float g_hT0[2][HD * BSZ];   // [h][b]
__device__ __align__(16) float g_hT1[2][HD * BSZ];
__device__ __align__(16) float g_cT0[HD * BSZ];
__device__ __align__(16) float g_cT1[HD * BSZ];
__device__ float g_pval[NGRP * BSZ];
__device__ int   g_pidx[NGRP * BSZ];
// duplicated-weight buffers: (w,w) packed in ull
__device__ ull g_WiT0[512 * 1024];   // [k][r] transposed-dup, 4MB
__device__ ull g_WhT0[256 * 1024];
__device__ ull g_WiT1[256 * 1024];
__device__ ull g_WhT1[256 * 1024];
__device__ ull g_Wod[(size_t)VD * 256];  // [v][k] dup, 65.5MB

// ---------------- helpers ----------------
__device__ __forceinline__ float dsig(float x) {
    return (float)(1.0 / (1.0 + exp(-(double)x)));
}
__device__ __forceinline__ float dth(float x) {
    return (float)tanh((double)x);
}
__device__ __forceinline__ ull ffma2(ull a, ull b, ull c) {
    ull d;
    asm("fma.rn.f32x2 %0, %1, %2, %3;" : "=l"(d) : "l"(a), "l"(b), "l"(c));
    return d;
}
__device__ __forceinline__ float2 unp(ull v) {
    float2 f;
    asm("mov.b64 {%0,%1}, %2;" : "=f"(f.x), "=f"(f.y) : "l"(v));
    return f;
}
__device__ __forceinline__ ull dup2(float w) {
    ull d;
    asm("mov.b64 %0, {%1,%1};" : "=l"(d) : "f"(w));
    return d;
}

// ================= weight duplication (per launch) =================
extern "C" __global__ void k_dupT(const float* __restrict__ W, ull* __restrict__ dst,
                                  int K, int total) {
    int id = blockIdx.x * 256 + threadIdx.x;
    if (id >= total) return;
    int k = id >> 10, r = id & 1023;
    dst[id] = dup2(W[(size_t)r * K + k]);     // dst[k*1024 + r]
}
extern "C" __global__ void k_dupO(const float* __restrict__ W) {
    size_t id = (size_t)blockIdx.x * 256 + threadIdx.x;
    if (id < (size_t)VD * 256) g_Wod[id] = dup2(W[id]);
}

// ================= pre + init: verbatim from passing R14 =================
extern "C" __global__ void k_pre(const float* __restrict__ enc) {
    int b = blockIdx.x, k = threadIdx.x;
    g_encT[k * BSZ + b] = enc[(size_t)b * 256 + k];
    if (b == 0) {
        if (k < BSZ) g_tok[k] = SOS;
        if (k == 0) { g_done = 0ULL; g_alldone = 0; }
    }
}

extern "C" __global__ void __launch_bounds__(128, 1)
k_init(const float* __restrict__ Wh, const float* __restrict__ bh,
       const float* __restrict__ Wc, const float* __restrict__ bc) {
    int t = threadIdx.x, w = t >> 5, L = t & 31;
    int which = w >> 1, hof = w & 1;
    int h = blockIdx.x * 2 + hof;
    const float* Wr = (which ? Wc : Wh) + (size_t)h * 256;
    float ax = 0.f, ay = 0.f;
#pragma unroll 4
    for (int k = 0; k < 256; k += 4) {
        float4 wv = *(const float4*)(Wr + k);
        float2 x0 = *(const float2*)&g_encT[(k + 0) * BSZ + 2 * L];
        float2 x1 = *(const float2*)&g_encT[(k + 1) * BSZ + 2 * L];
        float2 x2 = *(const float2*)&g_encT[(k + 2) * BSZ + 2 * L];
        float2 x3 = *(const float2*)&g_encT[(k + 3) * BSZ + 2 * L];
        ax = fmaf(wv.x, x0.x, ax); ay = fmaf(wv.x, x0.y, ay);
        ax = fmaf(wv.y, x1.x, ax); ay = fmaf(wv.y, x1.y, ay);
        ax = fmaf(wv.z, x2.x, ax); ay = fmaf(wv.z, x2.y, ay);
        ax = fmaf(wv.w, x3.x, ax); ay = fmaf(wv.w, x3.y, ay);
    }
    float bb = which ? bc[h] : bh[h];
    float2 v = make_float2(ax + bb, ay + bb);
    int idx = h * BSZ + 2 * L;
    if (which == 0) { *(float2*)&g_hT0[0][idx] = v; *(float2*)&g_hT1[0][idx] = v; }
    else            { *(float2*)&g_cT0[idx]    = v; *(float2*)&g_cT1[idx]    = v; }
}

// ================= fused LSTM (gates + cell), f32x2 =================
// grid 256 = 32 hgroups x 8 bgroups, 32 threads (1 warp).
// lane L: gate = L>>3, hloc = L&7 -> row r = hg*8+hloc + gate*256.
// Each lane: 1 row x 8 batches (4 f32x2 chains). Chain = Wih over Ei then Whh
// over 256, same accumulator, then +(bih+bhh): identical to R14 numerics.
extern "C" __global__ void __launch_bounds__(32, 8)
k_lstm(const ull* __restrict__ WiT, const ull* __restrict__ WhT,
       const float* __restrict__ bih, const float* __restrict__ bhh,
       const float* __restrict__ emb, int layer, int par)
{
    __shared__ float xs[512 * 8];
    __shared__ float hs[256 * 8];
    __shared__ float gsm[32 * 8];

    const int L = threadIdx.x;
    const int hg = blockIdx.x >> 3, bg = blockIdx.x & 7;
    const int b0 = bg * 8;
    const int gate = L >> 3, hloc = L & 7;
    const int h = hg * 8 + hloc;
    const int r = h + gate * HD;

    const float* hpv = (layer == 0) ? g_hT0[par] : g_hT1[par];
    float* cT   = (layer == 0) ? g_cT0 : g_cT1;
    float* hout = (layer == 0) ? g_hT0[par ^ 1] : g_hT1[par ^ 1];
    const int Ei = (layer == 0) ? ED : HD;

    // stage x
    if (layer == 0) {
        for (int j = 0; j < 8; j++) {
            const float* row = emb + (size_t)g_tok[b0 + j] * ED;
            for (int i = L; i < 128; i += 32) {
                float4 v = ((const float4*)row)[i];
                int k = i * 4;
                xs[k * 8 + j] = v.x; xs[(k + 1) * 8 + j] = v.y;
                xs[(k + 2) * 8 + j] = v.z; xs[(k + 3) * 8 + j] = v.w;
            }
        }
    } else {
        const float* src = g_hT0[par ^ 1];
        for (int i = L; i < 512; i += 32) {
            int k = i >> 1, hf = (i & 1) * 4;
            *(float4*)&xs[k * 8 + hf] = *(const float4*)&src[k * 64 + b0 + hf];
        }
    }
    // stage hprev
    for (int i = L; i < 512; i += 32) {
        int k = i >> 1, hf = (i & 1) * 4;
        *(float4*)&hs[k * 8 + hf] = *(const float4*)&hpv[k * 64 + b0 + hf];
    }
    __syncwarp();

    ull a0 = 0ULL, a1 = 0ULL, a2 = 0ULL, a3 = 0ULL;
#pragma unroll 8
    for (int k = 0; k < Ei; k++) {
        ull wk = WiT[(size_t)k * 1024 + r];
        ulonglong2 q0 = *(const ulonglong2*)&xs[k * 8];
        ulonglong2 q1 = *(const ulonglong2*)&xs[k * 8 + 4];
        a0 = ffma2(q0.x, wk, a0); a1 = ffma2(q0.y, wk, a1);
        a2 = ffma2(q1.x, wk, a2); a3 = ffma2(q1.y, wk, a3);
    }
#pragma unroll 8
    for (int k = 0; k < HD; k++) {
        ull wk = WhT[(size_t)k * 1024 + r];
        ulonglong2 q0 = *(const ulonglong2*)&hs[k * 8];
        ulonglong2 q1 = *(const ulonglong2*)&hs[k * 8 + 4];
        a0 = ffma2(q0.x, wk, a0); a1 = ffma2(q0.y, wk, a1);
        a2 = ffma2(q1.x, wk, a2); a3 = ffma2(q1.y, wk, a3);
    }
    float bb = bih[r] + bhh[r];
    float2 f0 = unp(a0), f1 = unp(a1), f2 = unp(a2), f3 = unp(a3);
    gsm[L * 8 + 0] = f0.x + bb; gsm[L * 8 + 1] = f0.y + bb;
    gsm[L * 8 + 2] = f1.x + bb; gsm[L * 8 + 3] = f1.y + bb;
    gsm[L * 8 + 4] = f2.x + bb; gsm[L * 8 + 5] = f2.y + bb;
    gsm[L * 8 + 6] = f3.x + bb; gsm[L * 8 + 7] = f3.y + bb;
    __syncwarp();

    // cell: 8h x 8b = 64 cells, 2 per lane (math verbatim from R14)
#pragma unroll
    for (int e = 0; e < 2; e++) {
        int cc = L * 2 + e;
        int hl = cc >> 3, bj = cc & 7;
        float gi = gsm[(0 * 8 + hl) * 8 + bj];
        float gf = gsm[(1 * 8 + hl) * 8 + bj];
        float gg = gsm[(2 * 8 + hl) * 8 + bj];
        float go = gsm[(3 * 8 + hl) * 8 + bj];
        int idx = (hg * 8 + hl) * 64 + b0 + bj;
        float c  = cT[idx];
        float cn = dsig(gf) * c + dsig(gi) * dth(gg);
        cT[idx] = cn;
        hout[idx] = dsig(go) * dth(cn);
    }
}

// ================= logits + per-block argmax, f32x2 =================
extern "C" __global__ void __launch_bounds__(256, 1)
k_logits(const float* __restrict__ bout, int par) {
    __shared__ ull  h1s[128 * 32];       // 32KB: [k][32 pairs]
    __shared__ float redv[8 * BSZ];
    __shared__ int   redi[8 * BSZ];
    int t = threadIdx.x, w = t >> 5, L = t & 31, grp = blockIdx.x;
    const float* h1g = g_hT1[par ^ 1];

    ull acc[8];
#pragma unroll
    for (int v = 0; v < 8; v++) acc[v] = 0ULL;

    const int vbase = grp * 64 + w * 8;
    const ull* wb = g_Wod + (size_t)vbase * 256;

    for (int half = 0; half < 2; half++) {
        __syncthreads();
        for (int i = t; i < 2048; i += 256)
            ((float4*)h1s)[i] = ((const float4*)(h1g + half * 128 * BSZ))[i];
        __syncthreads();
        const ull* wh = wb + half * 128;
#pragma unroll 2
        for (int k2 = 0; k2 < 64; k2++) {
            ull hq0 = h1s[(2 * k2) * 32 + L];
            ull hq1 = h1s[(2 * k2 + 1) * 32 + L];
#pragma unroll
            for (int v = 0; v < 8; v++) {
                ulonglong2 wd = *(const ulonglong2*)(wh + (size_t)v * 256 + 2 * k2);
                acc[v] = ffma2(hq0, wd.x, acc[v]);
                acc[v] = ffma2(hq1, wd.y, acc[v]);
            }
        }
    }

    float bvx = NEG_INF, bvy = NEG_INF;
    int bix = 0, biy = 0;
#pragma unroll
    for (int v = 0; v < 8; v++) {
        float bo = bout[vbase + v];
        float2 f = unp(acc[v]);
        float sx = f.x + bo, sy = f.y + bo;
        if (sx > bvx) { bvx = sx; bix = vbase + v; }   // ascending idx: first max
        if (sy > bvy) { bvy = sy; biy = vbase + v; }
    }
    redv[w * BSZ + 2 * L]     = bvx; redi[w * BSZ + 2 * L]     = bix;
    redv[w * BSZ + 2 * L + 1] = bvy; redi[w * BSZ + 2 * L + 1] = biy;
    __syncthreads();
    if (t < BSZ) {
        float bv = redv[t]; int bi = redi[t];
#pragma unroll
        for (int w2 = 1; w2 < 8; w2++) {
            float v = redv[w2 * BSZ + t]; int i2 = redi[w2 * BSZ + t];
            if (v > bv || (v == bv && i2 < bi)) { bv = v; bi = i2; }
        }
        g_pval[grp * BSZ + t] = bv;
        g_pidx[grp * BSZ + t] = bi;
    }
}

// ================= global argmax + token logic: verbatim R14 =================
extern "C" __global__ void __launch_bounds__(256, 1)
k_reduce(float* __restrict__ outp, int step) {
    __shared__ float redv[4 * BSZ];
    __shared__ int   redi[4 * BSZ];
    __shared__ unsigned sball[2];
    int t = threadIdx.x, b = t & 63, q = t >> 6;

    float bv = NEG_INF; int bi = 0x7fffffff;
    for (int p = q * 125; p < q * 125 + 125; p++) {
        float v = g_pval[p * BSZ + b]; int i2 = g_pidx[p * BSZ + b];
        if (v > bv || (v == bv && i2 < bi)) { bv = v; bi = i2; }
    }
    redv[q * BSZ + b] = bv; redi[q * BSZ + b] = bi;
    int adp = g_alldone;
    ull pdm = g_done;
    __syncthreads();
    if (t < BSZ) {
        bv = redv[t]; bi = redi[t];
#pragma unroll
        for (int q2 = 1; q2 < 4; q2++) {
            float v = redv[q2 * BSZ + t]; int i2 = redi[q2 * BSZ + t];
            if (v > bv || (v == bv && i2 < bi)) { bv = v; bi = i2; }
        }
        int out = adp ? 0 : bi;
        outp[t * MAXLEN + step] = (float)out;
        g_tok[t] = out;
        int nd = (int)((pdm >> t) & 1ULL) | (out == EOS);
        unsigned bal = __ballot_sync(0xffffffffu, nd != 0);
        if ((t & 31) == 0) sball[t >> 5] = bal;
    }
    __syncthreads();
    if (t == 0) {
        ull nm = (ull)sball[0] | ((ull)sball[1] << 32);
        g_done = nm;
        g_alldone = adp | (nm == 0xFFFFFFFFFFFFFFFFULL);
    }
}

// ================= host =================
static void* devptr(const void* sym) {
    void* p = 0; cudaGetSymbolAddress(&p, sym); return p;
}

extern "C" void kernel_launch(void* const* d_in, const int* in_sizes, int n_in,
                              void* d_out, int out_size) {
    (void)in_sizes; (void)n_in; (void)out_size;
    const float* enc  = (const float*)d_in[0];
    const float* emb  = (const float*)d_in[1];
    const float* Wh   = (const float*)d_in[2];
    const float* bh   = (const float*)d_in[3];
    const float* Wc   = (const float*)d_in[4];
    const float* bc   = (const float*)d_in[5];
    const float* Wih0 = (const float*)d_in[6];
    const float* Whh0 = (const float*)d_in[7];
    const float* bih0 = (const float*)d_in[8];
    const float* bhh0 = (const float*)d_in[9];
    const float* Wih1 = (const float*)d_in[10];
    const float* Whh1 = (const float*)d_in[11];
    const float* bih1 = (const float*)d_in[12];
    const float* bhh1 = (const float*)d_in[13];
    const float* Wout = (const float*)d_in[14];
    const float* bout = (const float*)d_in[15];
    float*       outp = (float*)d_out;

    ull* WiT0 = (ull*)devptr((const void*)g_WiT0);
    ull* WhT0 = (ull*)devptr((const void*)g_WhT0);
    ull* WiT1 = (ull*)devptr((const void*)g_WiT1);
    ull* WhT1 = (ull*)devptr((const void*)g_WhT1);

    k_dupT<<<2048, 256>>>(Wih0, WiT0, 512, 512 * 1024);
    k_dupT<<<1024, 256>>>(Whh0, WhT0, 256, 256 * 1024);
    k_dupT<<<1024, 256>>>(Wih1, WiT1, 256, 256 * 1024);
    k_dupT<<<1024, 256>>>(Whh1, WhT1, 256, 256 * 1024);
    k_dupO<<<32000, 256>>>(Wout);

    k_pre<<<64, 256>>>(enc);
    k_init<<<128, 128>>>(Wh, bh, Wc, bc);

    for (int s = 0; s < MAXLEN; s++) {
        int par = s & 1;
        k_lstm<<<256, 32>>>(WiT0, WhT0, bih0, bhh0, emb, 0, par);
        k_lstm<<<256, 32>>>(WiT1, WhT1, bih1, bhh1, emb, 1, par);
        k_logits<<<NGRP, 256>>>(bout, par);
        k_reduce<<<1, 256>>>(outp, s);
    }
}